// round 1
// baseline (speedup 1.0000x reference)
#include <cuda_runtime.h>
#include <math.h>
#include <stdint.h>

// Problem constants
#define Bq   2
#define Sq   2048
#define DM   1024
#define Hh   16
#define HD   64
#define MEMN 1000
#define KTOT 10

// ---------------- device scratch (no allocations allowed) ----------------
__device__ float g_q[Bq * Hh * Sq * HD];      // [B][H][S][HD]
__device__ float g_k[Bq * Hh * Sq * HD];
__device__ float g_v[Bq * Hh * Sq * HD];
__device__ float g_att[Bq * Sq * DM];          // [B][S][H*HD]
__device__ float g_ret[Bq * KTOT * DM];        // [B][K][H*HD]

// ---------------- tiled fp32 GEMM: C[M=4096,N=1024] = A @ W, K=1024 ------
#define BM 64
#define BN 64
#define BK 16
#define ASTRIDE (BM + 4)   // pad so float4 rows stay 16B-aligned, reduce bank conflicts

__global__ __launch_bounds__(256) void gemm64(const float* __restrict__ A,
                                              const float* __restrict__ W,
                                              float* __restrict__ C,
                                              int headwrite)
{
    const int Kd = 1024, Nd = 1024;
    __shared__ float As[BK][ASTRIDE];   // transposed A tile: As[k][m]
    __shared__ float Bs[BK][BN];

    int tid = threadIdx.x;
    int m0 = blockIdx.y * BM;
    int n0 = blockIdx.x * BN;
    int ty = tid >> 4, tx = tid & 15;

    int arow = tid >> 2;            // 0..63
    int ac4  = (tid & 3) * 4;       // 0,4,8,12
    int brw  = tid >> 4;            // 0..15
    int bc4  = (tid & 15) * 4;      // 0..60

    float acc[4][4];
#pragma unroll
    for (int i = 0; i < 4; i++)
#pragma unroll
        for (int j = 0; j < 4; j++) acc[i][j] = 0.f;

    for (int k0 = 0; k0 < Kd; k0 += BK) {
        float4 a = *(const float4*)&A[(size_t)(m0 + arow) * Kd + k0 + ac4];
        As[ac4 + 0][arow] = a.x;
        As[ac4 + 1][arow] = a.y;
        As[ac4 + 2][arow] = a.z;
        As[ac4 + 3][arow] = a.w;
        *(float4*)&Bs[brw][bc4] = *(const float4*)&W[(size_t)(k0 + brw) * Nd + n0 + bc4];
        __syncthreads();

#pragma unroll
        for (int kk = 0; kk < BK; kk++) {
            float4 av = *(const float4*)&As[kk][ty * 4];
            float4 bv = *(const float4*)&Bs[kk][tx * 4];
            acc[0][0] += av.x * bv.x; acc[0][1] += av.x * bv.y; acc[0][2] += av.x * bv.z; acc[0][3] += av.x * bv.w;
            acc[1][0] += av.y * bv.x; acc[1][1] += av.y * bv.y; acc[1][2] += av.y * bv.z; acc[1][3] += av.y * bv.w;
            acc[2][0] += av.z * bv.x; acc[2][1] += av.z * bv.y; acc[2][2] += av.z * bv.z; acc[2][3] += av.z * bv.w;
            acc[3][0] += av.w * bv.x; acc[3][1] += av.w * bv.y; acc[3][2] += av.w * bv.z; acc[3][3] += av.w * bv.w;
        }
        __syncthreads();
    }

#pragma unroll
    for (int i = 0; i < 4; i++) {
        int m = m0 + ty * 4 + i;
        int n = n0 + tx * 4;         // 4 consecutive cols, never cross a 64-head boundary
        float4 o = make_float4(acc[i][0], acc[i][1], acc[i][2], acc[i][3]);
        if (headwrite) {
            int b = m >> 11, s = m & 2047;
            int h = n >> 6,  hd = n & 63;
            *(float4*)&C[(((size_t)(b * Hh + h) * Sq) + s) * HD + hd] = o;
        } else {
            *(float4*)&C[(size_t)m * Nd + n] = o;
        }
    }
}

// ---------------- retrieval: cosine top-10 per batch ----------------------
__global__ __launch_bounds__(256) void retrieve_topk(const float* __restrict__ kbuf,
                                                     const float* __restrict__ events,
                                                     float* __restrict__ ret)
{
    int b = blockIdx.x;
    int tid = threadIdx.x;
    __shared__ float qs[DM];
    __shared__ float sims[MEMN];
    __shared__ float red[8];
    __shared__ float qn_s;
    __shared__ int   tidx[KTOT];

    // qvec = key of last token, heads concatenated
    for (int d = tid; d < DM; d += 256) {
        int h = d >> 6, hd = d & 63;
        qs[d] = kbuf[(((size_t)(b * Hh + h)) * Sq + (Sq - 1)) * HD + hd];
    }
    __syncthreads();

    float ps = 0.f;
    for (int d = tid; d < DM; d += 256) ps += qs[d] * qs[d];
#pragma unroll
    for (int off = 16; off > 0; off >>= 1) ps += __shfl_down_sync(0xffffffffu, ps, off);
    if ((tid & 31) == 0) red[tid >> 5] = ps;
    __syncthreads();
    if (tid == 0) {
        float t = 0.f;
        for (int w = 0; w < 8; w++) t += red[w];
        qn_s = sqrtf(t) + 1e-8f;
    }
    __syncthreads();
    float qnorm = qn_s;

    for (int e = tid; e < MEMN; e += 256) {
        const float* ep = events + (size_t)e * DM;
        float dot = 0.f, nn = 0.f;
        for (int d = 0; d < DM; d += 4) {
            float4 ev = *(const float4*)(ep + d);
            dot += qs[d] * ev.x + qs[d + 1] * ev.y + qs[d + 2] * ev.z + qs[d + 3] * ev.w;
            nn  += ev.x * ev.x + ev.y * ev.y + ev.z * ev.z + ev.w * ev.w;
        }
        sims[e] = dot / (qnorm * (sqrtf(nn) + 1e-8f));
    }
    __syncthreads();

    if (tid == 0) {
        for (int kk = 0; kk < KTOT; kk++) {
            float best = -1e30f; int bi = 0;
            for (int e = 0; e < MEMN; e++) {
                if (sims[e] > best) { best = sims[e]; bi = e; }  // strict > == lowest index on ties
            }
            tidx[kk] = bi;
            sims[bi] = -1e30f;
        }
    }
    __syncthreads();

    for (int kk = 0; kk < KTOT; kk++)
        for (int d = tid; d < DM; d += 256)
            ret[((size_t)b * KTOT + kk) * DM + d] = events[(size_t)tidx[kk] * DM + d];
}

// ---------------- flash attention: 1 CTA = 64 query rows of one (b,h) -----
#define TQ 64
#define TK 32

__global__ __launch_bounds__(64) void flash_attn(const float* __restrict__ amask,
                                                 const float* __restrict__ qbuf,
                                                 const float* __restrict__ kbuf,
                                                 const float* __restrict__ vbuf,
                                                 const float* __restrict__ ret,
                                                 float* __restrict__ att)
{
    __shared__ float Ks[TK][HD];
    __shared__ float Vs[TK][HD];
    __shared__ float Ss[TQ][TK + 1];
    __shared__ float mk[TK];

    int qt = gridDim.x - 1 - blockIdx.x;   // heavy tiles first (load balance)
    int h = blockIdx.y, b = blockIdx.z;
    int tid = threadIdx.x;
    int ig = qt * TQ + tid;                // global query row
    const float scale = 0.125f;            // 1/sqrt(64)
    float slope = exp2f(-0.5f * (float)(h + 1));

    // q row in registers
    float qreg[HD];
    {
        const float* qp = qbuf + (((size_t)(b * Hh + h)) * Sq + ig) * HD;
#pragma unroll
        for (int d = 0; d < HD; d += 4) {
            float4 t = *(const float4*)(qp + d);
            qreg[d] = t.x; qreg[d + 1] = t.y; qreg[d + 2] = t.z; qreg[d + 3] = t.w;
        }
    }

    float acc[HD];
#pragma unroll
    for (int d = 0; d < HD; d++) acc[d] = 0.f;
    float mrun = -1e30f, lrun = 0.f;

    // ---- memory tile: 10 always-visible tokens, zero bias ----
    {
        for (int idx = tid; idx < KTOT * HD; idx += 64) {
            int kk = idx >> 6, d = idx & 63;
            float val = ret[((size_t)b * KTOT + kk) * DM + h * HD + d];
            Ks[kk][d] = val;
            Vs[kk][d] = val;   // retrieved_v == retrieved_k
        }
        __syncthreads();

        float tmax = mrun;
        for (int j = 0; j < KTOT; j++) {
            float s = 0.f;
#pragma unroll
            for (int d = 0; d < HD; d += 4) {
                float4 kv = *(const float4*)&Ks[j][d];
                s += qreg[d] * kv.x + qreg[d + 1] * kv.y + qreg[d + 2] * kv.z + qreg[d + 3] * kv.w;
            }
            s *= scale;
            Ss[tid][j] = s;
            tmax = fmaxf(tmax, s);
        }
        float mnew = tmax;
        float corr = __expf(mrun - mnew);
        lrun *= corr;
#pragma unroll
        for (int d = 0; d < HD; d++) acc[d] *= corr;
        for (int j = 0; j < KTOT; j++) {
            float p = __expf(Ss[tid][j] - mnew);
            lrun += p;
#pragma unroll
            for (int d = 0; d < HD; d += 4) {
                float4 vv = *(const float4*)&Vs[j][d];
                acc[d] += p * vv.x; acc[d + 1] += p * vv.y; acc[d + 2] += p * vv.z; acc[d + 3] += p * vv.w;
            }
        }
        mrun = mnew;
        __syncthreads();
    }

    // ---- causal tiles ----
    int ktmax = (qt * TQ + TQ - 1) / TK;   // inclusive
    const float* kbase = kbuf + ((size_t)(b * Hh + h)) * Sq * HD;
    const float* vbase = vbuf + ((size_t)(b * Hh + h)) * Sq * HD;

    for (int kt = 0; kt <= ktmax; kt++) {
        int j0 = kt * TK;
        for (int idx = tid; idx < TK * (HD / 4); idx += 64) {
            int kk = idx >> 4, c4 = (idx & 15) * 4;
            *(float4*)&Ks[kk][c4] = *(const float4*)&kbase[(size_t)(j0 + kk) * HD + c4];
            *(float4*)&Vs[kk][c4] = *(const float4*)&vbase[(size_t)(j0 + kk) * HD + c4];
        }
        if (tid < TK) mk[tid] = amask[b * Sq + j0 + tid];
        __syncthreads();

        float tmax = mrun;
        for (int j = 0; j < TK; j++) {
            int jg = j0 + j;
            float s = 0.f;
#pragma unroll
            for (int d = 0; d < HD; d += 4) {
                float4 kv = *(const float4*)&Ks[j][d];
                s += qreg[d] * kv.x + qreg[d + 1] * kv.y + qreg[d + 2] * kv.z + qreg[d + 3] * kv.w;
            }
            s = s * scale + slope * (float)(ig - jg) + (1.0f - mk[j]) * (-1e9f);
            if (jg > ig) s = -1e30f;       // strictly-causal: excluded (exp underflows to 0)
            Ss[tid][j] = s;
            tmax = fmaxf(tmax, s);
        }
        float mnew = tmax;
        float corr = __expf(mrun - mnew);
        lrun *= corr;
#pragma unroll
        for (int d = 0; d < HD; d++) acc[d] *= corr;
        for (int j = 0; j < TK; j++) {
            float p = __expf(Ss[tid][j] - mnew);
            lrun += p;
#pragma unroll
            for (int d = 0; d < HD; d += 4) {
                float4 vv = *(const float4*)&Vs[j][d];
                acc[d] += p * vv.x; acc[d + 1] += p * vv.y; acc[d + 2] += p * vv.z; acc[d + 3] += p * vv.w;
            }
        }
        mrun = mnew;
        __syncthreads();
    }

    // ---- write [B,S,H*HD] for the output projection ----
    float inv = 1.0f / lrun;
    float* op = att + ((size_t)(b * Sq + ig)) * DM + h * HD;
#pragma unroll
    for (int d = 0; d < HD; d += 4) {
        float4 o = make_float4(acc[d] * inv, acc[d + 1] * inv, acc[d + 2] * inv, acc[d + 3] * inv);
        *(float4*)(op + d) = o;
    }
}

// ---------------- launcher ----------------
extern "C" void kernel_launch(void* const* d_in, const int* in_sizes, int n_in,
                              void* d_out, int out_size)
{
    const float* inputs = (const float*)d_in[0];
    const float* amask  = (const float*)d_in[1];
    const float* Wq     = (const float*)d_in[2];
    const float* Wk     = (const float*)d_in[3];
    const float* Wv     = (const float*)d_in[4];
    const float* Wo     = (const float*)d_in[5];
    const float* events = (const float*)d_in[6];
    float* out = (float*)d_out;

    float *q, *k, *v, *att, *ret;
    cudaGetSymbolAddress((void**)&q,   g_q);
    cudaGetSymbolAddress((void**)&k,   g_k);
    cudaGetSymbolAddress((void**)&v,   g_v);
    cudaGetSymbolAddress((void**)&att, g_att);
    cudaGetSymbolAddress((void**)&ret, g_ret);

    dim3 gg(DM / BN, (Bq * Sq) / BM);   // (16, 64)

    gemm64<<<gg, 256>>>(inputs, Wq, q, 1);
    gemm64<<<gg, 256>>>(inputs, Wk, k, 1);
    gemm64<<<gg, 256>>>(inputs, Wv, v, 1);

    retrieve_topk<<<Bq, 256>>>(k, events, ret);

    flash_attn<<<dim3(Sq / TQ, Hh, Bq), 64>>>(amask, q, k, v, ret, att);

    gemm64<<<gg, 256>>>(att, Wo, out, 0);
}

// round 2
// speedup vs baseline: 1.7208x; 1.7208x over previous
#include <cuda_runtime.h>
#include <math.h>
#include <stdint.h>

// Problem constants
#define Bq   2
#define Sq   2048
#define DM   1024
#define Hh   16
#define HD   64
#define MEMN 1000
#define KTOT 10

// ---------------- device scratch ----------------
__device__ float g_q[Bq * Hh * Sq * HD];
__device__ float g_k[Bq * Hh * Sq * HD];
__device__ float g_v[Bq * Hh * Sq * HD];
__device__ float g_att[Bq * Sq * DM];
__device__ float g_ret[Bq * KTOT * DM];
__device__ float g_sims[Bq * MEMN];

// ---------------- helpers ----------------
__device__ __forceinline__ float cf_tf32(float x) {
    uint32_t u;
    asm("cvt.rna.tf32.f32 %0, %1;" : "=r"(u) : "f"(x));
    return __uint_as_float(u);
}
__device__ __forceinline__ void mma8(float* c, const uint32_t* a, const uint32_t* b) {
    asm("mma.sync.aligned.m16n8k8.row.col.f32.tf32.tf32.f32 "
        "{%0,%1,%2,%3},{%4,%5,%6,%7},{%8,%9},{%0,%1,%2,%3};"
        : "+f"(c[0]), "+f"(c[1]), "+f"(c[2]), "+f"(c[3])
        : "r"(a[0]), "r"(a[1]), "r"(a[2]), "r"(a[3]), "r"(b[0]), "r"(b[1]));
}
__device__ __forceinline__ uint64_t pk2(float a, float b) {
    uint64_t r;
    asm("mov.b64 %0,{%1,%2};" : "=l"(r) : "f"(a), "f"(b));
    return r;
}
__device__ __forceinline__ void upk2(float& a, float& b, uint64_t v) {
    asm("mov.b64 {%0,%1},%2;" : "=f"(a), "=f"(b) : "l"(v));
}
__device__ __forceinline__ void fma2(uint64_t& d, uint64_t a, uint64_t b) {
    asm("fma.rn.f32x2 %0,%1,%2,%0;" : "+l"(d) : "l"(a), "l"(b));
}
__device__ __forceinline__ void mul2(uint64_t& d, uint64_t a) {
    asm("mul.rn.f32x2 %0,%0,%1;" : "+l"(d) : "l"(a));
}

// ---------------- tf32 tensor-core GEMM: C[4096,1024] = A @ W, K=1024 -----
#define GBM 128
#define GBN 128
#define GBK 16
#define ASTR (GBM + 4)
#define BSTR (GBN + 4)

__global__ __launch_bounds__(256) void gemm_tf32(const float* __restrict__ A,
                                                 const float* __restrict__ W,
                                                 float* __restrict__ C,
                                                 int headwrite)
{
    __shared__ float As[GBK][ASTR];   // As[k][m]
    __shared__ float Bs[GBK][BSTR];   // Bs[k][n]

    const int Kd = 1024, Nd = 1024;
    int tid = threadIdx.x;
    int lane = tid & 31, wid = tid >> 5;
    int wm = wid & 3;          // 0..3 -> rows wm*32
    int wn = wid >> 2;         // 0..1 -> cols wn*64
    int m0 = blockIdx.y * GBM;
    int n0 = blockIdx.x * GBN;

    // stage-load indices
    int arow = tid >> 1;             // 0..127
    int akc  = (tid & 1) * 8;        // 0 or 8
    int bkr  = tid >> 4;             // 0..15
    int bc4  = (tid & 15) * 4;       // 0..60

    float acc[2][8][4];
#pragma unroll
    for (int i = 0; i < 2; i++)
#pragma unroll
        for (int j = 0; j < 8; j++)
#pragma unroll
            for (int t = 0; t < 4; t++) acc[i][j][t] = 0.f;

    const float* Ap = A + (size_t)(m0 + arow) * Kd + akc;
    const float* Wp = W + (size_t)bkr * Nd + n0 + bc4;

    float4 pa0 = *(const float4*)(Ap);
    float4 pa1 = *(const float4*)(Ap + 4);
    float4 pw0 = *(const float4*)(Wp);
    float4 pw1 = *(const float4*)(Wp + 64);

    for (int k0 = 0; k0 < Kd; k0 += GBK) {
        // stage (with tf32 rounding)
        As[akc + 0][arow] = cf_tf32(pa0.x);
        As[akc + 1][arow] = cf_tf32(pa0.y);
        As[akc + 2][arow] = cf_tf32(pa0.z);
        As[akc + 3][arow] = cf_tf32(pa0.w);
        As[akc + 4][arow] = cf_tf32(pa1.x);
        As[akc + 5][arow] = cf_tf32(pa1.y);
        As[akc + 6][arow] = cf_tf32(pa1.z);
        As[akc + 7][arow] = cf_tf32(pa1.w);
        float4 w0 = make_float4(cf_tf32(pw0.x), cf_tf32(pw0.y), cf_tf32(pw0.z), cf_tf32(pw0.w));
        float4 w1 = make_float4(cf_tf32(pw1.x), cf_tf32(pw1.y), cf_tf32(pw1.z), cf_tf32(pw1.w));
        *(float4*)&Bs[bkr][bc4]      = w0;
        *(float4*)&Bs[bkr][bc4 + 64] = w1;
        __syncthreads();

        if (k0 + GBK < Kd) {
            pa0 = *(const float4*)(Ap + k0 + GBK);
            pa1 = *(const float4*)(Ap + k0 + GBK + 4);
            pw0 = *(const float4*)(Wp + (size_t)(k0 + GBK) * Nd);
            pw1 = *(const float4*)(Wp + (size_t)(k0 + GBK) * Nd + 64);
        }

        int r = lane >> 2, c = lane & 3;
#pragma unroll
        for (int ks = 0; ks < GBK; ks += 8) {
            uint32_t af[2][4];
#pragma unroll
            for (int i = 0; i < 2; i++) {
                int mb = wm * 32 + i * 16 + r;
                af[i][0] = __float_as_uint(As[ks + c][mb]);
                af[i][1] = __float_as_uint(As[ks + c][mb + 8]);
                af[i][2] = __float_as_uint(As[ks + c + 4][mb]);
                af[i][3] = __float_as_uint(As[ks + c + 4][mb + 8]);
            }
            uint32_t bf[8][2];
#pragma unroll
            for (int j = 0; j < 8; j++) {
                int nb = wn * 64 + j * 8 + r;
                bf[j][0] = __float_as_uint(Bs[ks + c][nb]);
                bf[j][1] = __float_as_uint(Bs[ks + c + 4][nb]);
            }
#pragma unroll
            for (int i = 0; i < 2; i++)
#pragma unroll
                for (int j = 0; j < 8; j++) mma8(acc[i][j], af[i], bf[j]);
        }
        __syncthreads();
    }

    // epilogue: each warp owns a 32x64 region; 64-col region = exactly one head
    int r = lane >> 2, c2 = (lane & 3) * 2;
#pragma unroll
    for (int i = 0; i < 2; i++) {
#pragma unroll
        for (int j = 0; j < 8; j++) {
            int row0 = m0 + wm * 32 + i * 16 + r;
            int col  = n0 + wn * 64 + j * 8 + c2;
            float2 lo = make_float2(acc[i][j][0], acc[i][j][1]);
            float2 hi = make_float2(acc[i][j][2], acc[i][j][3]);
            if (headwrite) {
                int b = row0 >> 11, h = col >> 6, hd = col & 63;
                int s0 = row0 & 2047;
                float* base = C + (((size_t)(b * Hh + h)) * Sq) * HD + hd;
                *(float2*)(base + (size_t)s0 * HD)       = lo;
                *(float2*)(base + (size_t)(s0 + 8) * HD) = hi;
            } else {
                *(float2*)&C[(size_t)row0 * Nd + col]       = lo;
                *(float2*)&C[(size_t)(row0 + 8) * Nd + col] = hi;
            }
        }
    }
}

// ---------------- retrieval: sims (warp per event) ------------------------
__global__ __launch_bounds__(256) void retrieve_sims(const float* __restrict__ kbuf,
                                                     const float* __restrict__ events,
                                                     float* __restrict__ sims)
{
    int b = blockIdx.y;
    int tid = threadIdx.x;
    int lane = tid & 31, wid = tid >> 5;
    __shared__ float qs[DM];
    __shared__ float qn_s;

    for (int d = tid; d < DM; d += 256) {
        int h = d >> 6, hd = d & 63;
        qs[d] = kbuf[(((size_t)(b * Hh + h)) * Sq + (Sq - 1)) * HD + hd];
    }
    __syncthreads();
    if (wid == 0) {
        float ps = 0.f;
        for (int d = lane * 4; d < DM; d += 128) {
            float4 t = *(const float4*)&qs[d];
            ps += t.x * t.x + t.y * t.y + t.z * t.z + t.w * t.w;
        }
#pragma unroll
        for (int off = 16; off > 0; off >>= 1) ps += __shfl_down_sync(0xffffffffu, ps, off);
        if (lane == 0) qn_s = sqrtf(ps) + 1e-8f;
    }
    __syncthreads();
    float qnorm = qn_s;

    int e = blockIdx.x * 8 + wid;
    if (e >= MEMN) return;
    const float* ep = events + (size_t)e * DM;
    float dot = 0.f, nn = 0.f;
    for (int d = lane * 4; d < DM; d += 128) {
        float4 ev = *(const float4*)(ep + d);
        float4 qv = *(const float4*)&qs[d];
        dot += qv.x * ev.x + qv.y * ev.y + qv.z * ev.z + qv.w * ev.w;
        nn  += ev.x * ev.x + ev.y * ev.y + ev.z * ev.z + ev.w * ev.w;
    }
#pragma unroll
    for (int off = 16; off > 0; off >>= 1) {
        dot += __shfl_down_sync(0xffffffffu, dot, off);
        nn  += __shfl_down_sync(0xffffffffu, nn, off);
    }
    if (lane == 0) sims[b * MEMN + e] = dot / (qnorm * (sqrtf(nn) + 1e-8f));
}

// ---------------- retrieval: parallel top-k + gather -----------------------
__global__ __launch_bounds__(256) void topk_gather(const float* __restrict__ sims,
                                                   const float* __restrict__ events,
                                                   float* __restrict__ ret)
{
    int b = blockIdx.x;
    int tid = threadIdx.x;
    int lane = tid & 31, wid = tid >> 5;
    __shared__ float sv[MEMN];
    __shared__ float wmax[8];
    __shared__ int   widx[8];
    __shared__ int   tidx[KTOT];

    for (int e = tid; e < MEMN; e += 256) sv[e] = sims[b * MEMN + e];
    __syncthreads();

    for (int kk = 0; kk < KTOT; kk++) {
        float bm = -1e30f; int bi = MEMN;
        for (int e = tid; e < MEMN; e += 256) {
            float v = sv[e];
            if (v > bm || (v == bm && e < bi)) { bm = v; bi = e; }
        }
#pragma unroll
        for (int off = 16; off > 0; off >>= 1) {
            float om = __shfl_down_sync(0xffffffffu, bm, off);
            int   oi = __shfl_down_sync(0xffffffffu, bi, off);
            if (om > bm || (om == bm && oi < bi)) { bm = om; bi = oi; }
        }
        if (lane == 0) { wmax[wid] = bm; widx[wid] = bi; }
        __syncthreads();
        if (tid == 0) {
            float gm = wmax[0]; int gi = widx[0];
            for (int w = 1; w < 8; w++) {
                if (wmax[w] > gm || (wmax[w] == gm && widx[w] < gi)) { gm = wmax[w]; gi = widx[w]; }
            }
            tidx[kk] = gi;
            sv[gi] = -1e30f;
        }
        __syncthreads();
    }

    for (int kk = 0; kk < KTOT; kk++) {
        int src = tidx[kk];
        for (int d = tid; d < DM; d += 256)
            ret[((size_t)b * KTOT + kk) * DM + d] = events[(size_t)src * DM + d];
    }
}

// ---------------- flash attention: 128 rows/CTA, f32x2 inner loops ---------
#define TQ 128
#define TK 32

__global__ __launch_bounds__(128) void flash_attn(const float* __restrict__ amask,
                                                  const float* __restrict__ qbuf,
                                                  const float* __restrict__ kbuf,
                                                  const float* __restrict__ vbuf,
                                                  const float* __restrict__ ret,
                                                  float* __restrict__ att)
{
    __shared__ float Ks[TK][HD];
    __shared__ float Vs[TK][HD];
    __shared__ float Ss[TQ][TK + 1];
    __shared__ float mk[TK];

    int qt = gridDim.x - 1 - blockIdx.x;   // heavy tiles first
    int h = blockIdx.y, b = blockIdx.z;
    int tid = threadIdx.x;
    int ig = qt * TQ + tid;
    const float scale = 0.125f;
    float slope = exp2f(-0.5f * (float)(h + 1));

    uint64_t q2[HD / 2];
    {
        const float* qp = qbuf + (((size_t)(b * Hh + h)) * Sq + ig) * HD;
#pragma unroll
        for (int d = 0; d < HD; d += 4) {
            float4 t = *(const float4*)(qp + d);
            q2[d >> 1]       = pk2(t.x, t.y);
            q2[(d >> 1) + 1] = pk2(t.z, t.w);
        }
    }

    uint64_t acc2[HD / 2];
#pragma unroll
    for (int i = 0; i < HD / 2; i++) acc2[i] = 0ull;
    float mrun = -1e30f, lrun = 0.f;

    // ---- memory tile ----
    {
        for (int idx = tid; idx < KTOT * HD; idx += TQ) {
            int kk = idx >> 6, d = idx & 63;
            float val = ret[((size_t)b * KTOT + kk) * DM + h * HD + d];
            Ks[kk][d] = val;
            Vs[kk][d] = val;
        }
        __syncthreads();

        float tmax = mrun;
        for (int j = 0; j < KTOT; j++) {
            uint64_t s2a = 0ull, s2b = 0ull;
#pragma unroll
            for (int d = 0; d < HD; d += 4) {
                ulonglong2 kv = *(const ulonglong2*)&Ks[j][d];
                fma2(s2a, q2[d >> 1], kv.x);
                fma2(s2b, q2[(d >> 1) + 1], kv.y);
            }
            float ax, ay, bx, by;
            upk2(ax, ay, s2a); upk2(bx, by, s2b);
            float s = (ax + ay + bx + by) * scale;
            Ss[tid][j] = s;
            tmax = fmaxf(tmax, s);
        }
        float mnew = tmax;
        float corr = __expf(mrun - mnew);
        lrun *= corr;
        uint64_t cd = pk2(corr, corr);
#pragma unroll
        for (int i = 0; i < HD / 2; i++) mul2(acc2[i], cd);
        for (int j = 0; j < KTOT; j++) {
            float p = __expf(Ss[tid][j] - mnew);
            lrun += p;
            uint64_t pd = pk2(p, p);
#pragma unroll
            for (int d = 0; d < HD; d += 4) {
                ulonglong2 vv = *(const ulonglong2*)&Vs[j][d];
                fma2(acc2[d >> 1], pd, vv.x);
                fma2(acc2[(d >> 1) + 1], pd, vv.y);
            }
        }
        mrun = mnew;
        __syncthreads();
    }

    // ---- causal tiles ----
    int ktmax = (qt * TQ + TQ - 1) / TK;
    const float* kbase = kbuf + ((size_t)(b * Hh + h)) * Sq * HD;
    const float* vbase = vbuf + ((size_t)(b * Hh + h)) * Sq * HD;

    for (int kt = 0; kt <= ktmax; kt++) {
        int j0 = kt * TK;
        for (int idx = tid; idx < TK * (HD / 4); idx += TQ) {
            int kk = idx >> 4, c4 = (idx & 15) * 4;
            *(float4*)&Ks[kk][c4] = *(const float4*)&kbase[(size_t)(j0 + kk) * HD + c4];
            *(float4*)&Vs[kk][c4] = *(const float4*)&vbase[(size_t)(j0 + kk) * HD + c4];
        }
        if (tid < TK) mk[tid] = amask[b * Sq + j0 + tid];
        __syncthreads();

        float tmax = mrun;
        for (int j = 0; j < TK; j++) {
            int jg = j0 + j;
            uint64_t s2a = 0ull, s2b = 0ull;
#pragma unroll
            for (int d = 0; d < HD; d += 4) {
                ulonglong2 kv = *(const ulonglong2*)&Ks[j][d];
                fma2(s2a, q2[d >> 1], kv.x);
                fma2(s2b, q2[(d >> 1) + 1], kv.y);
            }
            float ax, ay, bx, by;
            upk2(ax, ay, s2a); upk2(bx, by, s2b);
            float s = (ax + ay + bx + by) * scale + slope * (float)(ig - jg)
                      + (1.0f - mk[j]) * (-1e9f);
            if (jg > ig) s = -1e30f;
            Ss[tid][j] = s;
            tmax = fmaxf(tmax, s);
        }
        float mnew = tmax;
        float corr = __expf(mrun - mnew);
        lrun *= corr;
        uint64_t cd = pk2(corr, corr);
#pragma unroll
        for (int i = 0; i < HD / 2; i++) mul2(acc2[i], cd);
        for (int j = 0; j < TK; j++) {
            float p = __expf(Ss[tid][j] - mnew);
            lrun += p;
            uint64_t pd = pk2(p, p);
#pragma unroll
            for (int d = 0; d < HD; d += 4) {
                ulonglong2 vv = *(const ulonglong2*)&Vs[j][d];
                fma2(acc2[d >> 1], pd, vv.x);
                fma2(acc2[(d >> 1) + 1], pd, vv.y);
            }
        }
        mrun = mnew;
        __syncthreads();
    }

    float inv = 1.0f / lrun;
    float* op = att + ((size_t)(b * Sq + ig)) * DM + h * HD;
#pragma unroll
    for (int d = 0; d < HD; d += 4) {
        float x0, x1, x2, x3;
        upk2(x0, x1, acc2[d >> 1]);
        upk2(x2, x3, acc2[(d >> 1) + 1]);
        *(float4*)(op + d) = make_float4(x0 * inv, x1 * inv, x2 * inv, x3 * inv);
    }
}

// ---------------- launcher ----------------
extern "C" void kernel_launch(void* const* d_in, const int* in_sizes, int n_in,
                              void* d_out, int out_size)
{
    const float* inputs = (const float*)d_in[0];
    const float* amask  = (const float*)d_in[1];
    const float* Wq     = (const float*)d_in[2];
    const float* Wk     = (const float*)d_in[3];
    const float* Wv     = (const float*)d_in[4];
    const float* Wo     = (const float*)d_in[5];
    const float* events = (const float*)d_in[6];
    float* out = (float*)d_out;

    float *q, *k, *v, *att, *ret, *sims;
    cudaGetSymbolAddress((void**)&q,    g_q);
    cudaGetSymbolAddress((void**)&k,    g_k);
    cudaGetSymbolAddress((void**)&v,    g_v);
    cudaGetSymbolAddress((void**)&att,  g_att);
    cudaGetSymbolAddress((void**)&ret,  g_ret);
    cudaGetSymbolAddress((void**)&sims, g_sims);

    dim3 gg(DM / GBN, (Bq * Sq) / GBM);   // (8, 32)

    gemm_tf32<<<gg, 256>>>(inputs, Wq, q, 1);
    gemm_tf32<<<gg, 256>>>(inputs, Wk, k, 1);
    gemm_tf32<<<gg, 256>>>(inputs, Wv, v, 1);

    retrieve_sims<<<dim3(125, Bq), 256>>>(k, events, sims);
    topk_gather<<<Bq, 256>>>(sims, events, ret);

    flash_attn<<<dim3(Sq / TQ, Hh, Bq), TQ>>>(amask, q, k, v, ret, att);

    gemm_tf32<<<gg, 256>>>(att, Wo, out, 0);
}

// round 4
// speedup vs baseline: 1.7936x; 1.0423x over previous
#include <cuda_runtime.h>
#include <math.h>
#include <stdint.h>

// Problem constants
#define Bq   2
#define Sq   2048
#define DM   1024
#define Hh   16
#define HD   64
#define MEMN 1000
#define KTOT 10

// ---------------- device scratch ----------------
__device__ float g_q[Bq * Hh * Sq * HD];
__device__ float g_k[Bq * Hh * Sq * HD];
__device__ float g_v[Bq * Hh * Sq * HD];
__device__ float g_att[Bq * Sq * DM];
__device__ float g_ret[Bq * KTOT * DM];
__device__ float g_sims[Bq * MEMN];
__device__ float g_wt[4 * DM * DM];    // transposed weights [N][K] x4

// ---------------- helpers ----------------
__device__ __forceinline__ uint32_t smem_u32(const void* p) {
    uint32_t a;
    asm("{ .reg .u64 t; cvta.to.shared.u64 t, %1; cvt.u32.u64 %0, t; }" : "=r"(a) : "l"(p));
    return a;
}
__device__ __forceinline__ float cf_tf32(float x) {
    uint32_t u;
    asm("cvt.rna.tf32.f32 %0, %1;" : "=r"(u) : "f"(x));
    return __uint_as_float(u);
}
__device__ __forceinline__ void mma8(float* c, const uint32_t* a, const uint32_t* b) {
    asm("mma.sync.aligned.m16n8k8.row.col.f32.tf32.tf32.f32 "
        "{%0,%1,%2,%3},{%4,%5,%6,%7},{%8,%9},{%0,%1,%2,%3};"
        : "+f"(c[0]), "+f"(c[1]), "+f"(c[2]), "+f"(c[3])
        : "r"(a[0]), "r"(a[1]), "r"(a[2]), "r"(a[3]), "r"(b[0]), "r"(b[1]));
}
__device__ __forceinline__ uint64_t pk2(float a, float b) {
    uint64_t r; asm("mov.b64 %0,{%1,%2};" : "=l"(r) : "f"(a), "f"(b)); return r;
}
__device__ __forceinline__ void upk2(float& a, float& b, uint64_t v) {
    asm("mov.b64 {%0,%1},%2;" : "=f"(a), "=f"(b) : "l"(v));
}
__device__ __forceinline__ void fma2(uint64_t& d, uint64_t a, uint64_t b) {
    asm("fma.rn.f32x2 %0,%1,%2,%0;" : "+l"(d) : "l"(a), "l"(b));
}
__device__ __forceinline__ void mul2(uint64_t& d, uint64_t a) {
    asm("mul.rn.f32x2 %0,%0,%1;" : "+l"(d) : "l"(a));
}
__device__ __forceinline__ void cpa16(uint32_t d, const void* g) {
    asm volatile("cp.async.cg.shared.global [%0], [%1], 16;" :: "r"(d), "l"(g) : "memory");
}
#define CP_COMMIT() asm volatile("cp.async.commit_group;" ::: "memory")

// ---------------- weight transpose: WT[z][n][k] = W_z[k][n] ----------------
__global__ __launch_bounds__(256) void transpose_w(const float* __restrict__ W0,
                                                   const float* __restrict__ W1,
                                                   const float* __restrict__ W2,
                                                   const float* __restrict__ W3,
                                                   float* __restrict__ WT)
{
    __shared__ float t[32][33];
    int z = blockIdx.z;
    const float* W = (z == 0) ? W0 : (z == 1) ? W1 : (z == 2) ? W2 : W3;
    float* D = WT + (size_t)z * DM * DM;
    int x = blockIdx.x * 32, y = blockIdx.y * 32;
    int tx = threadIdx.x & 31, ty = threadIdx.x >> 5;
    for (int r = ty; r < 32; r += 8)
        t[r][tx] = W[(size_t)(y + r) * DM + x + tx];
    __syncthreads();
    for (int r = ty; r < 32; r += 8)
        D[(size_t)(x + r) * DM + y + tx] = t[tx][r];
}

// ---------------- cp.async-pipelined tf32 mma.sync GEMM -------------------
// C[4096,1024] = A[4096,1024] @ WT[1024,1024]^T   (WT is [N][K])
// tile 128x128x16, 3-stage pipeline, 256 threads, 2 CTAs/SM.
#define GP      20                    // padded row stride (floats): conflict-free
#define STGF    (128 * GP * 2)        // floats per stage (A + B)
#define NSTAGE  3
#define NIT     (DM / 16)             // 64
#define GSMEM_BYTES (NSTAGE * STGF * 4)

__global__ void __launch_bounds__(256, 2) gemm_cp(const float* __restrict__ A,
                                                  const float* __restrict__ WT,
                                                  float* __restrict__ C,
                                                  int headwrite)
{
    extern __shared__ float dsm[];
    uint32_t sbase = smem_u32(dsm);

    int tid = threadIdx.x, lane = tid & 31, wid = tid >> 5;
    int wm = wid & 3, wn = wid >> 2;
    int m0 = blockIdx.y * 128, n0 = blockIdx.x * 128;
    int r = lane >> 2, c = lane & 3;

    // staging assignment: each thread loads 8 floats (2x16B) of A and of B
    int srow = tid >> 1, shalf = tid & 1;
    const float* gA = A  + (size_t)(m0 + srow) * DM + shalf * 8;
    const float* gB = WT + (size_t)(n0 + srow) * DM + shalf * 8;
    uint32_t dA = sbase + (uint32_t)(srow * GP + shalf * 8) * 4u;
    uint32_t dB = dA + (uint32_t)(128 * GP) * 4u;

    float acc[2][8][4];
#pragma unroll
    for (int i = 0; i < 2; i++)
#pragma unroll
        for (int j = 0; j < 8; j++)
#pragma unroll
            for (int t = 0; t < 4; t++) acc[i][j][t] = 0.f;

    // prologue: stages 0, 1
#pragma unroll
    for (int s = 0; s < NSTAGE - 1; s++) {
        uint32_t so = (uint32_t)(s * STGF) * 4u;
        cpa16(dA + so,      gA + s * 16);
        cpa16(dA + so + 16, gA + s * 16 + 4);
        cpa16(dB + so,      gB + s * 16);
        cpa16(dB + so + 16, gB + s * 16 + 4);
        CP_COMMIT();
    }

    for (int it = 0; it < NIT; ++it) {
        if (it + NSTAGE - 1 < NIT) {
            int s = it + NSTAGE - 1;
            uint32_t so = (uint32_t)((s % NSTAGE) * STGF) * 4u;
            cpa16(dA + so,      gA + s * 16);
            cpa16(dA + so + 16, gA + s * 16 + 4);
            cpa16(dB + so,      gB + s * 16);
            cpa16(dB + so + 16, gB + s * 16 + 4);
            CP_COMMIT();
        }
        if (it <= NIT - 3)      asm volatile("cp.async.wait_group 2;" ::: "memory");
        else if (it == NIT - 2) asm volatile("cp.async.wait_group 1;" ::: "memory");
        else                    asm volatile("cp.async.wait_group 0;" ::: "memory");
        __syncthreads();

        const float* As = dsm + (it % NSTAGE) * STGF;
        const float* Bs = As + 128 * GP;

#pragma unroll
        for (int ks = 0; ks < 16; ks += 8) {
            uint32_t af[2][4];
#pragma unroll
            for (int i = 0; i < 2; i++) {
                int row = wm * 32 + i * 16 + r;
                af[i][0] = __float_as_uint(cf_tf32(As[row * GP + ks + c]));
                af[i][1] = __float_as_uint(cf_tf32(As[(row + 8) * GP + ks + c]));
                af[i][2] = __float_as_uint(cf_tf32(As[row * GP + ks + c + 4]));
                af[i][3] = __float_as_uint(cf_tf32(As[(row + 8) * GP + ks + c + 4]));
            }
            uint32_t bf[8][2];
#pragma unroll
            for (int j = 0; j < 8; j++) {
                int nr = wn * 64 + j * 8 + r;
                bf[j][0] = __float_as_uint(cf_tf32(Bs[nr * GP + ks + c]));
                bf[j][1] = __float_as_uint(cf_tf32(Bs[nr * GP + ks + c + 4]));
            }
#pragma unroll
            for (int i = 0; i < 2; i++)
#pragma unroll
                for (int j = 0; j < 8; j++) mma8(acc[i][j], af[i], bf[j]);
        }
        __syncthreads();
    }

    // epilogue: warp owns 32x64; 64-col region = one head
    int c2 = (lane & 3) * 2;
#pragma unroll
    for (int i = 0; i < 2; i++) {
#pragma unroll
        for (int j = 0; j < 8; j++) {
            int row0 = m0 + wm * 32 + i * 16 + r;
            int col  = n0 + wn * 64 + j * 8 + c2;
            float2 lo = make_float2(acc[i][j][0], acc[i][j][1]);
            float2 hi = make_float2(acc[i][j][2], acc[i][j][3]);
            if (headwrite) {
                int b = row0 >> 11, h = col >> 6, hd = col & 63;
                int s0 = row0 & 2047;
                float* base = C + (((size_t)(b * Hh + h)) * Sq) * HD + hd;
                *(float2*)(base + (size_t)s0 * HD)       = lo;
                *(float2*)(base + (size_t)(s0 + 8) * HD) = hi;
            } else {
                *(float2*)&C[(size_t)row0 * DM + col]       = lo;
                *(float2*)&C[(size_t)(row0 + 8) * DM + col] = hi;
            }
        }
    }
}

// ---------------- retrieval: sims (warp per event) ------------------------
__global__ __launch_bounds__(256) void retrieve_sims(const float* __restrict__ kbuf,
                                                     const float* __restrict__ events,
                                                     float* __restrict__ sims)
{
    int b = blockIdx.y;
    int tid = threadIdx.x;
    int lane = tid & 31, wid = tid >> 5;
    __shared__ float qs[DM];
    __shared__ float qn_s;

    for (int d = tid; d < DM; d += 256) {
        int h = d >> 6, hd = d & 63;
        qs[d] = kbuf[(((size_t)(b * Hh + h)) * Sq + (Sq - 1)) * HD + hd];
    }
    __syncthreads();
    if (wid == 0) {
        float ps = 0.f;
        for (int d = lane * 4; d < DM; d += 128) {
            float4 t = *(const float4*)&qs[d];
            ps += t.x * t.x + t.y * t.y + t.z * t.z + t.w * t.w;
        }
#pragma unroll
        for (int off = 16; off > 0; off >>= 1) ps += __shfl_down_sync(0xffffffffu, ps, off);
        if (lane == 0) qn_s = sqrtf(ps) + 1e-8f;
    }
    __syncthreads();
    float qnorm = qn_s;

    int e = blockIdx.x * 8 + wid;
    if (e >= MEMN) return;
    const float* ep = events + (size_t)e * DM;
    float dot = 0.f, nn = 0.f;
    for (int d = lane * 4; d < DM; d += 128) {
        float4 ev = *(const float4*)(ep + d);
        float4 qv = *(const float4*)&qs[d];
        dot += qv.x * ev.x + qv.y * ev.y + qv.z * ev.z + qv.w * ev.w;
        nn  += ev.x * ev.x + ev.y * ev.y + ev.z * ev.z + ev.w * ev.w;
    }
#pragma unroll
    for (int off = 16; off > 0; off >>= 1) {
        dot += __shfl_down_sync(0xffffffffu, dot, off);
        nn  += __shfl_down_sync(0xffffffffu, nn, off);
    }
    if (lane == 0) sims[b * MEMN + e] = dot / (qnorm * (sqrtf(nn) + 1e-8f));
}

// ---------------- retrieval: parallel top-k + gather -----------------------
__global__ __launch_bounds__(256) void topk_gather(const float* __restrict__ sims,
                                                   const float* __restrict__ events,
                                                   float* __restrict__ ret)
{
    int b = blockIdx.x;
    int tid = threadIdx.x;
    int lane = tid & 31, wid = tid >> 5;
    __shared__ float sv[MEMN];
    __shared__ float wmax[8];
    __shared__ int   widx[8];
    __shared__ int   tidx[KTOT];

    for (int e = tid; e < MEMN; e += 256) sv[e] = sims[b * MEMN + e];
    __syncthreads();

    for (int kk = 0; kk < KTOT; kk++) {
        float bm = -1e30f; int bi = MEMN;
        for (int e = tid; e < MEMN; e += 256) {
            float v = sv[e];
            if (v > bm || (v == bm && e < bi)) { bm = v; bi = e; }
        }
#pragma unroll
        for (int off = 16; off > 0; off >>= 1) {
            float om = __shfl_down_sync(0xffffffffu, bm, off);
            int   oi = __shfl_down_sync(0xffffffffu, bi, off);
            if (om > bm || (om == bm && oi < bi)) { bm = om; bi = oi; }
        }
        if (lane == 0) { wmax[wid] = bm; widx[wid] = bi; }
        __syncthreads();
        if (tid == 0) {
            float gm = wmax[0]; int gi = widx[0];
            for (int w = 1; w < 8; w++) {
                if (wmax[w] > gm || (wmax[w] == gm && widx[w] < gi)) { gm = wmax[w]; gi = widx[w]; }
            }
            tidx[kk] = gi;
            sv[gi] = -1e30f;
        }
        __syncthreads();
    }

    for (int kk = 0; kk < KTOT; kk++) {
        int src = tidx[kk];
        for (int d = tid; d < DM; d += 256)
            ret[((size_t)b * KTOT + kk) * DM + d] = events[(size_t)src * DM + d];
    }
}

// ---------------- flash attention: 128 rows/CTA, f32x2 inner loops ---------
#define TQ 128
#define TK 32

__global__ __launch_bounds__(128) void flash_attn(const float* __restrict__ amask,
                                                  const float* __restrict__ qbuf,
                                                  const float* __restrict__ kbuf,
                                                  const float* __restrict__ vbuf,
                                                  const float* __restrict__ ret,
                                                  float* __restrict__ att)
{
    __shared__ float Ks[TK][HD];
    __shared__ float Vs[TK][HD];
    __shared__ float Ss[TQ][TK + 1];
    __shared__ float mk[TK];

    int qt = gridDim.x - 1 - blockIdx.x;
    int h = blockIdx.y, b = blockIdx.z;
    int tid = threadIdx.x;
    int ig = qt * TQ + tid;
    const float scale = 0.125f;
    float slope = exp2f(-0.5f * (float)(h + 1));

    uint64_t q2[HD / 2];
    {
        const float* qp = qbuf + (((size_t)(b * Hh + h)) * Sq + ig) * HD;
#pragma unroll
        for (int d = 0; d < HD; d += 4) {
            float4 t = *(const float4*)(qp + d);
            q2[d >> 1]       = pk2(t.x, t.y);
            q2[(d >> 1) + 1] = pk2(t.z, t.w);
        }
    }

    uint64_t acc2[HD / 2];
#pragma unroll
    for (int i = 0; i < HD / 2; i++) acc2[i] = 0ull;
    float mrun = -1e30f, lrun = 0.f;

    // ---- memory tile ----
    {
        for (int idx = tid; idx < KTOT * HD; idx += TQ) {
            int kk = idx >> 6, d = idx & 63;
            float val = ret[((size_t)b * KTOT + kk) * DM + h * HD + d];
            Ks[kk][d] = val;
            Vs[kk][d] = val;
        }
        __syncthreads();

        float tmax = mrun;
        for (int j = 0; j < KTOT; j++) {
            uint64_t s2a = 0ull, s2b = 0ull;
#pragma unroll
            for (int d = 0; d < HD; d += 4) {
                ulonglong2 kv = *(const ulonglong2*)&Ks[j][d];
                fma2(s2a, q2[d >> 1], kv.x);
                fma2(s2b, q2[(d >> 1) + 1], kv.y);
            }
            float ax, ay, bx, by;
            upk2(ax, ay, s2a); upk2(bx, by, s2b);
            float s = (ax + ay + bx + by) * scale;
            Ss[tid][j] = s;
            tmax = fmaxf(tmax, s);
        }
        float mnew = tmax;
        float corr = __expf(mrun - mnew);
        lrun *= corr;
        uint64_t cd = pk2(corr, corr);
#pragma unroll
        for (int i = 0; i < HD / 2; i++) mul2(acc2[i], cd);
        for (int j = 0; j < KTOT; j++) {
            float p = __expf(Ss[tid][j] - mnew);
            lrun += p;
            uint64_t pd = pk2(p, p);
#pragma unroll
            for (int d = 0; d < HD; d += 4) {
                ulonglong2 vv = *(const ulonglong2*)&Vs[j][d];
                fma2(acc2[d >> 1], pd, vv.x);
                fma2(acc2[(d >> 1) + 1], pd, vv.y);
            }
        }
        mrun = mnew;
        __syncthreads();
    }

    // ---- causal tiles ----
    int ktmax = (qt * TQ + TQ - 1) / TK;
    const float* kbase = kbuf + ((size_t)(b * Hh + h)) * Sq * HD;
    const float* vbase = vbuf + ((size_t)(b * Hh + h)) * Sq * HD;

    for (int kt = 0; kt <= ktmax; kt++) {
        int j0 = kt * TK;
        for (int idx = tid; idx < TK * (HD / 4); idx += TQ) {
            int kk = idx >> 4, c4 = (idx & 15) * 4;
            *(float4*)&Ks[kk][c4] = *(const float4*)&kbase[(size_t)(j0 + kk) * HD + c4];
            *(float4*)&Vs[kk][c4] = *(const float4*)&vbase[(size_t)(j0 + kk) * HD + c4];
        }
        if (tid < TK) mk[tid] = amask[b * Sq + j0 + tid];
        __syncthreads();

        float tmax = mrun;
        for (int j = 0; j < TK; j++) {
            int jg = j0 + j;
            uint64_t s2a = 0ull, s2b = 0ull;
#pragma unroll
            for (int d = 0; d < HD; d += 4) {
                ulonglong2 kv = *(const ulonglong2*)&Ks[j][d];
                fma2(s2a, q2[d >> 1], kv.x);
                fma2(s2b, q2[(d >> 1) + 1], kv.y);
            }
            float ax, ay, bx, by;
            upk2(ax, ay, s2a); upk2(bx, by, s2b);
            float s = (ax + ay + bx + by) * scale + slope * (float)(ig - jg)
                      + (1.0f - mk[j]) * (-1e9f);
            if (jg > ig) s = -1e30f;
            Ss[tid][j] = s;
            tmax = fmaxf(tmax, s);
        }
        float mnew = tmax;
        float corr = __expf(mrun - mnew);
        lrun *= corr;
        uint64_t cd = pk2(corr, corr);
#pragma unroll
        for (int i = 0; i < HD / 2; i++) mul2(acc2[i], cd);
        for (int j = 0; j < TK; j++) {
            float p = __expf(Ss[tid][j] - mnew);
            lrun += p;
            uint64_t pd = pk2(p, p);
#pragma unroll
            for (int d = 0; d < HD; d += 4) {
                ulonglong2 vv = *(const ulonglong2*)&Vs[j][d];
                fma2(acc2[d >> 1], pd, vv.x);
                fma2(acc2[(d >> 1) + 1], pd, vv.y);
            }
        }
        mrun = mnew;
        __syncthreads();
    }

    float inv = 1.0f / lrun;
    float* op = att + ((size_t)(b * Sq + ig)) * DM + h * HD;
#pragma unroll
    for (int d = 0; d < HD; d += 4) {
        float x0, x1, x2, x3;
        upk2(x0, x1, acc2[d >> 1]);
        upk2(x2, x3, acc2[(d >> 1) + 1]);
        *(float4*)(op + d) = make_float4(x0 * inv, x1 * inv, x2 * inv, x3 * inv);
    }
}

// ---------------- launcher ----------------
extern "C" void kernel_launch(void* const* d_in, const int* in_sizes, int n_in,
                              void* d_out, int out_size)
{
    const float* inputs = (const float*)d_in[0];
    const float* amask  = (const float*)d_in[1];
    const float* Wq     = (const float*)d_in[2];
    const float* Wk     = (const float*)d_in[3];
    const float* Wv     = (const float*)d_in[4];
    const float* Wo     = (const float*)d_in[5];
    const float* events = (const float*)d_in[6];
    float* out = (float*)d_out;

    float *q, *k, *v, *att, *ret, *sims, *wt;
    cudaGetSymbolAddress((void**)&q,    g_q);
    cudaGetSymbolAddress((void**)&k,    g_k);
    cudaGetSymbolAddress((void**)&v,    g_v);
    cudaGetSymbolAddress((void**)&att,  g_att);
    cudaGetSymbolAddress((void**)&ret,  g_ret);
    cudaGetSymbolAddress((void**)&sims, g_sims);
    cudaGetSymbolAddress((void**)&wt,   g_wt);

    cudaFuncSetAttribute(gemm_cp, cudaFuncAttributeMaxDynamicSharedMemorySize, GSMEM_BYTES);

    transpose_w<<<dim3(32, 32, 4), 256>>>(Wq, Wk, Wv, Wo, wt);

    dim3 gg(DM / 128, (Bq * Sq) / 128);   // (8, 32)
    gemm_cp<<<gg, 256, GSMEM_BYTES>>>(inputs, wt + 0 * DM * DM, q, 1);
    gemm_cp<<<gg, 256, GSMEM_BYTES>>>(inputs, wt + 1 * DM * DM, k, 1);
    gemm_cp<<<gg, 256, GSMEM_BYTES>>>(inputs, wt + 2 * DM * DM, v, 1);

    retrieve_sims<<<dim3(125, Bq), 256>>>(k, events, sims);
    topk_gather<<<Bq, 256>>>(sims, events, ret);

    flash_attn<<<dim3(Sq / TQ, Hh, Bq), TQ>>>(amask, q, k, v, ret, att);

    gemm_cp<<<gg, 256, GSMEM_BYTES>>>(att, wt + 3 * DM * DM, out, 0);
}